// round 11
// baseline (speedup 1.0000x reference)
#include <cuda_runtime.h>
#include <math.h>
#include <math_constants.h>

#define C_CLASSES 1000
#define NVEC      (C_CLASSES / 4)   // 250 float4 per row
#define THREADS   256
#define WPB       (THREADS / 32)    // 8 warps
#define NPAIR     (WPB / 2)         // 4 warp-pairs per block
#define NBLK      740               // 5 blocks/SM * 148 SMs = one full wave
#define MAGIC     0.165745444183859f

__device__ float g_partials[NBLK];

// ---------------------------------------------------------------------------
// Main kernel: fused scalar prep + per-row logsumexp, one row per WARP PAIR.
// 16 data regs/thread -> 5 CTAs/SM (40 warps, 62.5% occ) vs 4 CTAs at v[8].
// Deterministic block partials; no atomics; no cross-block sync.
// ---------------------------------------------------------------------------
__global__ void __launch_bounds__(THREADS, 5)
fused_loss_kernel(const float* __restrict__ x,
                  const int*   __restrict__ targets,
                  const float* __restrict__ cls,
                  const float* __restrict__ diff,
                  const int*   __restrict__ epoch_p,
                  int nB, int nC)
{
    const int tid  = threadIdx.x;
    const int lane = tid & 31;
    const int wid  = tid >> 5;
    const int pair = wid >> 1;          // 0..3 pair within block
    const int wip  = wid & 1;           // warp-in-pair
    const int p    = tid & 63;          // lane within the 64-thread pair

    const int gpair = blockIdx.x * NPAIR + pair;
    const int totp  = gridDim.x * NPAIR;

    // pair exchange buffers (separate arrays -> no cross-iteration hazard)
    __shared__ float xm[NPAIR][2];
    __shared__ float xs[NPAIR][2];

    // ---- Prefetch row 0 BEFORE the prep barrier ---------------------------
    int    row  = gpair;
    bool   have = (row < nB);
    float4 v[4];
    float  xt = 0.0f, ct = 1.0f, dt = 0.0f;
    if (have) {
        const int t = __ldg(targets + row);
        const float* xrow = x + (size_t)row * C_CLASSES;
        xt = __ldg(xrow + t);
        ct = __ldg(cls + t);
        dt = __ldg(diff + t);
        const float4* xr = reinterpret_cast<const float4*>(xrow);
        #pragma unroll
        for (int j = 0; j < 3; j++)
            v[j] = __ldg(xr + p + 64 * j);
        int idx = p + 192;
        if (idx < NVEC) v[3] = __ldg(xr + idx);
        else            v[3] = make_float4(-1e30f, -1e30f, -1e30f, -1e30f);
    }

    // ---- Phase 0: per-block redundant scalar prep (L2-hot, 1000 elems) ----
    __shared__ float s_mn[WPB], s_sm[WPB], s_mx[WPB];
    __shared__ float s_scalars[3];
    {
        float mn = CUDART_INF_F, sm = 0.0f, mx = -CUDART_INF_F;
        for (int i = tid; i < nC; i += THREADS) {
            float c = __ldg(cls + i);
            float d = __ldg(diff + i);
            mn = fminf(mn, c);
            sm += c;
            mx = fmaxf(mx, 0.5f * d * d + 0.3f);
        }
        #pragma unroll
        for (int o = 16; o; o >>= 1) {
            mn = fminf(mn, __shfl_xor_sync(0xffffffffu, mn, o));
            sm += __shfl_xor_sync(0xffffffffu, sm, o);
            mx = fmaxf(mx, __shfl_xor_sync(0xffffffffu, mx, o));
        }
        if (lane == 0) { s_mn[wid] = mn; s_sm[wid] = sm; s_mx[wid] = mx; }
        __syncthreads();
        if (tid == 0) {
            mn = s_mn[0]; sm = s_sm[0]; mx = s_mx[0];
            #pragma unroll
            for (int i = 1; i < WPB; i++) {
                mn = fminf(mn, s_mn[i]);
                sm += s_sm[i];
                mx = fmaxf(mx, s_mx[i]);
            }
            s_scalars[0] = mn; s_scalars[1] = sm; s_scalars[2] = mx;
        }
        __syncthreads();
    }

    const float min_c = s_scalars[0];
    const float sum_c = s_scalars[1];
    const float wmax  = s_scalars[2];
    const float max_m = -logf(min_c / sum_c) - MAGIC;

    const int epoch = epoch_p ? __ldg(epoch_p) : 70;
    float ee = 0.0f;
    if (epoch >= 60) ee = (epoch >= 80) ? 1.0f : (float)(epoch - 60) * (1.0f / 20.0f);
    const float wscale = ee * 0.5f * max_m / wmax;

    // ---- Phase 1: stream rows, one per warp pair --------------------------
    float acc = 0.0f;
    const int bar_id = pair + 1;        // named barriers 1..4 (64 threads each)

    #pragma unroll 1
    while (have) {
        // Local max over this warp's half of the row.
        float mw = -CUDART_INF_F;
        #pragma unroll
        for (int j = 0; j < 4; j++)
            mw = fmaxf(mw, fmaxf(fmaxf(v[j].x, v[j].y), fmaxf(v[j].z, v[j].w)));
        #pragma unroll
        for (int o = 16; o; o >>= 1)
            mw = fmaxf(mw, __shfl_xor_sync(0xffffffffu, mw, o));

        // Pair combine for the max.
        if (lane == 0) xm[pair][wip] = mw;
        asm volatile("bar.sync %0, %1;" :: "r"(bar_id), "r"(64) : "memory");
        const float m = fmaxf(xm[pair][0], xm[pair][1]);

        // Independent exps over this warp's half (last read of v).
        float sw = 0.0f;
        #pragma unroll
        for (int j = 0; j < 4; j++) {
            sw += __expf(v[j].x - m) + __expf(v[j].y - m)
                + __expf(v[j].z - m) + __expf(v[j].w - m);
        }

        // v dead: prefetch next row so the reduce/margin tail overlaps DRAM.
        const float xt_c = xt, ct_c = ct, dt_c = dt;
        row += totp;
        have = (row < nB);
        if (have) {
            const int t = __ldg(targets + row);
            const float* xrow = x + (size_t)row * C_CLASSES;
            xt = __ldg(xrow + t);
            ct = __ldg(cls + t);
            dt = __ldg(diff + t);
            const float4* xr = reinterpret_cast<const float4*>(xrow);
            #pragma unroll
            for (int j = 0; j < 3; j++)
                v[j] = __ldg(xr + p + 64 * j);
            int idx = p + 192;
            if (idx < NVEC) v[3] = __ldg(xr + idx);
            else            v[3] = make_float4(-1e30f, -1e30f, -1e30f, -1e30f);
        }

        // Intra-warp sum, then pair combine.
        #pragma unroll
        for (int o = 16; o; o >>= 1)
            sw += __shfl_xor_sync(0xffffffffu, sw, o);
        if (lane == 0) xs[pair][wip] = sw;
        asm volatile("bar.sync %0, %1;" :: "r"(bar_id), "r"(64) : "memory");

        // Only warp 0 of the pair accumulates (avoids double count).
        if (wip == 0) {
            const float s = xs[pair][0] + xs[pair][1];
            const float margin = max_m * sqrtf(min_c / ct_c)
                               + (0.5f * dt_c * dt_c + 0.3f) * wscale;
            const float xta  = xt_c - margin;
            const float sadj = s + __expf(xt_c - m) * (__expf(-margin) - 1.0f);
            acc += (m + __logf(sadj)) - xta;
        }
    }

    // ---- Phase 2: block partial (deterministic) ---------------------------
    __shared__ float sacc[NPAIR];
    if (wip == 0 && lane == 0) sacc[pair] = acc;
    __syncthreads();
    if (tid == 0) {
        float tot = 0.0f;
        #pragma unroll
        for (int i = 0; i < NPAIR; i++) tot += sacc[i];
        g_partials[blockIdx.x] = tot;
    }
}

// ---------------------------------------------------------------------------
// Finalize: reduce NBLK partials -> mean loss. One block.
// ---------------------------------------------------------------------------
__global__ void finalize_kernel(float* __restrict__ out, int nB) {
    __shared__ float sh[THREADS / 32];
    int tid = threadIdx.x;
    float v = 0.0f;
    for (int i = tid; i < NBLK; i += THREADS)
        v += g_partials[i];
    #pragma unroll
    for (int o = 16; o; o >>= 1)
        v += __shfl_xor_sync(0xffffffffu, v, o);
    if ((tid & 31) == 0) sh[tid >> 5] = v;
    __syncthreads();
    if (tid < 32) {
        v = (tid < THREADS / 32) ? sh[tid] : 0.0f;
        #pragma unroll
        for (int o = 16; o; o >>= 1)
            v += __shfl_xor_sync(0xffffffffu, v, o);
        if (tid == 0) out[0] = v / (float)nB;
    }
}

// ---------------------------------------------------------------------------
extern "C" void kernel_launch(void* const* d_in, const int* in_sizes, int n_in,
                              void* d_out, int out_size) {
    const float* x       = (const float*)d_in[0];
    const int*   targets = (const int*)  d_in[1];
    const float* cls     = (const float*)d_in[2];
    const float* diff    = (const float*)d_in[3];
    const int*   epoch   = (n_in >= 5) ? (const int*)d_in[4] : nullptr;

    int nB = in_sizes[1];
    int nC = in_sizes[2];
    float* out = (float*)d_out;

    fused_loss_kernel<<<NBLK, THREADS>>>(x, targets, cls, diff, epoch, nB, nC);
    finalize_kernel<<<1, THREADS>>>(out, nB);
}